// round 4
// baseline (speedup 1.0000x reference)
#include <cuda_runtime.h>
#include <stdint.h>

// Sparse Adagrad on GB300 (sm_103a).
//
// Output layout (matches reference return order): out[0:V*D] = weights_new,
// out[V*D:2*V*D] = moments_new.
//
// Phase 0: D2D memcpy weights/moments into out (512 MB bulk traffic).
// Phase 1: moments_new[idx[i]] += g[i]^2          (atomicAdd, valid rows only)
// Phase 2: w_new[idx[i]] -= lr*g[i]/(sqrt(m_new[idx[i]])+eps)   (after phase 1;
//          stream ordering provides the grid-wide barrier)
//
// indices: JAX downcasts jnp.int64 -> int32 when x64 is disabled (default),
// so they arrive as int32.
// valid_count is a static python int (200000) per the reference; hardcoded.

#define EPS 1e-10f
#define D 64
#define VALID_COUNT 200000

__global__ void moment_scatter_kernel(const float4* __restrict__ g,   // [N, D/4]
                                      const int* __restrict__ idx,    // [N] int32
                                      float* __restrict__ m_out)      // out + V*D
{
    // one thread per float4 chunk: VALID_COUNT * (D/4) threads
    long t = (long)blockIdx.x * blockDim.x + threadIdx.x;
    long total = (long)VALID_COUNT * (D / 4);
    if (t >= total) return;
    long row = t >> 4;          // D/4 = 16 chunks per row
    int chunk = (int)(t & 15);

    long v = (long)idx[row];
    float4 gv = g[row * (D / 4) + chunk];
    float* dst = m_out + v * D + chunk * 4;
    atomicAdd(dst + 0, gv.x * gv.x);
    atomicAdd(dst + 1, gv.y * gv.y);
    atomicAdd(dst + 2, gv.z * gv.z);
    atomicAdd(dst + 3, gv.w * gv.w);
}

__global__ void weight_scatter_kernel(const float4* __restrict__ g,
                                      const int* __restrict__ idx,
                                      const float* __restrict__ lr_ptr,
                                      const float4* __restrict__ m_out, // out + V*D (final moments)
                                      float* __restrict__ w_out)        // out
{
    long t = (long)blockIdx.x * blockDim.x + threadIdx.x;
    long total = (long)VALID_COUNT * (D / 4);
    if (t >= total) return;
    long row = t >> 4;
    int chunk = (int)(t & 15);

    float lr = *lr_ptr;
    long v = (long)idx[row];
    float4 gv = g[row * (D / 4) + chunk];
    float4 mv = m_out[v * (D / 4) + chunk];

    float dx = -lr * gv.x / (sqrtf(mv.x) + EPS);
    float dy = -lr * gv.y / (sqrtf(mv.y) + EPS);
    float dz = -lr * gv.z / (sqrtf(mv.z) + EPS);
    float dw = -lr * gv.w / (sqrtf(mv.w) + EPS);

    float* dst = w_out + v * D + chunk * 4;
    atomicAdd(dst + 0, dx);
    atomicAdd(dst + 1, dy);
    atomicAdd(dst + 2, dz);
    atomicAdd(dst + 3, dw);
}

extern "C" void kernel_launch(void* const* d_in, const int* in_sizes, int n_in,
                              void* d_out, int out_size)
{
    const float* gradients = (const float*)d_in[0];   // [N, 64]
    const float* weights   = (const float*)d_in[1];   // [V, 64]
    const float* moments   = (const float*)d_in[2];   // [V, 64]
    const int*   indices   = (const int*)d_in[3];     // [N] int32 (see note above)
    const float* lr        = (const float*)d_in[4];   // scalar

    long VD = (long)in_sizes[1];          // V*D = 32,000,000
    float* out_w = (float*)d_out;         // weights_new
    float* out_m = (float*)d_out + VD;    // moments_new

    // Phase 0: bulk copy both regions (512 MB total traffic), D2D async —
    // graph-capturable and hits the LTS/HBM ceiling.
    cudaMemcpyAsync(out_w, weights, VD * sizeof(float), cudaMemcpyDeviceToDevice);
    cudaMemcpyAsync(out_m, moments, VD * sizeof(float), cudaMemcpyDeviceToDevice);

    // Phase 1: accumulate squared gradients into moments_new
    {
        long total = (long)VALID_COUNT * (D / 4);   // 3.2M threads
        int threads = 256;
        int blocks = (int)((total + threads - 1) / threads);
        moment_scatter_kernel<<<blocks, threads>>>((const float4*)gradients,
                                                   indices, out_m);
    }

    // Phase 2: weight update using fully-accumulated moments (stream-ordered
    // after phase 1)
    {
        long total = (long)VALID_COUNT * (D / 4);
        int threads = 256;
        int blocks = (int)((total + threads - 1) / threads);
        weight_scatter_kernel<<<blocks, threads>>>((const float4*)gradients,
                                                   indices, lr,
                                                   (const float4*)out_m, out_w);
    }
}

// round 7
// speedup vs baseline: 1.6754x; 1.6754x over previous
#include <cuda_runtime.h>
#include <stdint.h>

// Sparse Adagrad on GB300 (sm_103a) — gather formulation.
//
// Identity: all duplicate occurrences of index v share the same fully
// accumulated denominator, so
//   m_new[v] = m[v] + sum_i g_i^2
//   w_new[v] = w[v] - lr * (sum_i g_i) / (sqrt(m_new[v]) + eps)
// One fused pass over output rows computes both, reading w/m once and
// writing once. The inverse index map is built as per-bucket linked
// lists (head[V] + next[N]) — no prefix scan required.
//
// Output layout: out[0:V*D] = weights_new, out[V*D:2*V*D] = moments_new.
// indices arrive as int32 (JAX x64 disabled). valid_count=200000 static.

#define EPS 1e-10f
#define D 64
#define CHUNKS 16            // D/4 float4 chunks per row
#define VALID_COUNT 200000
#define V_MAX 500000
#define N_MAX 262144

__device__ int g_head[V_MAX];   // head of linked list per vocab row (-1 = empty)
__device__ int g_next[N_MAX];   // next gradient row in same bucket

__global__ void init_head_kernel(int V)
{
    int stride = gridDim.x * blockDim.x;
    for (int v = blockIdx.x * blockDim.x + threadIdx.x; v < V; v += stride)
        g_head[v] = -1;
}

__global__ void build_lists_kernel(const int* __restrict__ idx)
{
    int i = blockIdx.x * blockDim.x + threadIdx.x;
    if (i >= VALID_COUNT) return;
    int v = idx[i];
    g_next[i] = atomicExch(&g_head[v], i);
}

__global__ void fused_adagrad_kernel(const float4* __restrict__ g,   // [N, 16]
                                     const float4* __restrict__ w,   // [V, 16]
                                     const float4* __restrict__ m,   // [V, 16]
                                     const float* __restrict__ lr_ptr,
                                     float4* __restrict__ out_w,     // [V, 16]
                                     float4* __restrict__ out_m,     // [V, 16]
                                     int V)
{
    long t = (long)blockIdx.x * blockDim.x + threadIdx.x;
    long total = (long)V * CHUNKS;
    if (t >= total) return;
    int v = (int)(t >> 4);        // output row
    int chunk = (int)(t & 15);
    long off = (long)v * CHUNKS + chunk;

    float lr = __ldg(lr_ptr);     // L1-resident scalar; hoisted off the rare path
    float4 mv = m[off];
    float4 wv = w[off];

    int i = __ldg(&g_head[v]);    // broadcast within the 16-thread group
    if (i >= 0) {
        float4 sg  = make_float4(0.f, 0.f, 0.f, 0.f);
        float4 sg2 = make_float4(0.f, 0.f, 0.f, 0.f);
        do {
            float4 gv = g[(long)i * CHUNKS + chunk];
            sg.x += gv.x;  sg.y += gv.y;  sg.z += gv.z;  sg.w += gv.w;
            sg2.x = fmaf(gv.x, gv.x, sg2.x);
            sg2.y = fmaf(gv.y, gv.y, sg2.y);
            sg2.z = fmaf(gv.z, gv.z, sg2.z);
            sg2.w = fmaf(gv.w, gv.w, sg2.w);
            i = __ldg(&g_next[i]);
        } while (i >= 0);

        mv.x += sg2.x;  mv.y += sg2.y;  mv.z += sg2.z;  mv.w += sg2.w;

        wv.x -= lr * sg.x / (sqrtf(mv.x) + EPS);
        wv.y -= lr * sg.y / (sqrtf(mv.y) + EPS);
        wv.z -= lr * sg.z / (sqrtf(mv.z) + EPS);
        wv.w -= lr * sg.w / (sqrtf(mv.w) + EPS);
    }

    out_w[off] = wv;
    out_m[off] = mv;
}

extern "C" void kernel_launch(void* const* d_in, const int* in_sizes, int n_in,
                              void* d_out, int out_size)
{
    const float* gradients = (const float*)d_in[0];   // [N, 64]
    const float* weights   = (const float*)d_in[1];   // [V, 64]
    const float* moments   = (const float*)d_in[2];   // [V, 64]
    const int*   indices   = (const int*)d_in[3];     // [N] int32
    const float* lr        = (const float*)d_in[4];   // scalar

    long VD = (long)in_sizes[1];          // V*D = 32,000,000
    int  V  = (int)(VD / D);              // 500,000
    float* out_w = (float*)d_out;
    float* out_m = (float*)d_out + VD;

    // 1. reset bucket heads (2 MB)
    init_head_kernel<<<592, 256>>>(V);

    // 2. build per-bucket linked lists over valid gradient rows
    build_lists_kernel<<<(VALID_COUNT + 255) / 256, 256>>>(indices);

    // 3. fused gather + update + write (single full pass over output)
    {
        long total = (long)V * CHUNKS;    // 8M threads
        int threads = 256;
        int blocks = (int)((total + threads - 1) / threads);
        fused_adagrad_kernel<<<blocks, threads>>>((const float4*)gradients,
                                                  (const float4*)weights,
                                                  (const float4*)moments,
                                                  lr,
                                                  (float4*)out_w,
                                                  (float4*)out_m,
                                                  V);
    }
}